// round 11
// baseline (speedup 1.0000x reference)
#include <cuda_runtime.h>
#include <cuda_fp16.h>
#include <math.h>
#include <stdint.h>

// BlurredNoise via mma.sync fp16 (m16n8k16) implicit GEMM, 2-pass split.
// R11: KB=64 (half the syncs/staging rounds), software-pipelined A-fragment
// loads (next k16-step prefetched under current MMAs), interleaved {hi,lo}
// window words (LDS.64). Per-n8-tile zero-prefix skip kept from R10.

#define KS      5000
#define IN_SEQ  9095
#define T_OUT   4096
#define NFILT   128
#define NROWS   16
#define NG      4
#define NF      32      // filters per group (GEMM N)
#define MT      256     // t per CTA (GEMM M)
#define THREADS 128
#define KB      64      // taps per chunk (4 k16 steps)
#define SXP_LEN 5328    // >= max prefetch index 5325
#define BROW    33      // uint pairs per filter row per chunk (32 + 1 pad)
#define BCH     (NF * BROW)

struct StartArr { int klo[NG]; int st[NG][4]; };

__device__ __forceinline__ uint32_t packh2(float a, float b) {
    __half2 h = __halves2half2(__float2half_rn(a), __float2half_rn(b));
    return *reinterpret_cast<uint32_t*>(&h);
}

__device__ __forceinline__ void mma_f16(float* d,
                                        uint32_t a0, uint32_t a1,
                                        uint32_t a2, uint32_t a3,
                                        uint32_t b0, uint32_t b1) {
    asm volatile(
        "mma.sync.aligned.m16n8k16.row.col.f32.f16.f16.f32 "
        "{%0,%1,%2,%3}, {%4,%5,%6,%7}, {%8,%9}, {%0,%1,%2,%3};"
        : "+f"(d[0]), "+f"(d[1]), "+f"(d[2]), "+f"(d[3])
        : "r"(a0), "r"(a1), "r"(a2), "r"(a3), "r"(b0), "r"(b1));
}

extern __shared__ char smem_raw[];

__global__ __launch_bounds__(THREADS)
void blur_mma_kernel(const float* __restrict__ noise,
                     const float* __restrict__ filt,
                     const float* __restrict__ scale,
                     float* __restrict__ out,
                     StartArr sa)
{
    uint2*    sPhl = reinterpret_cast<uint2*>(smem_raw);            // {h2, l2}
    uint32_t* sBp  = reinterpret_cast<uint32_t*>(smem_raw + SXP_LEN * 8);
    float*    ss   = reinterpret_cast<float*>(smem_raw + SXP_LEN * 8 + 2 * BCH * 4);

    const int tid  = threadIdx.x;
    const int g    = (NG - 1) - blockIdx.x;     // heavy group first
    const int tb   = blockIdx.y;
    const int row  = blockIdx.z;

    const int t0   = tb * MT;
    const int f0   = g * NF;
    const int klo  = sa.klo[g];                 // may be negative (zero pad)
    const int nch  = (KS - klo) / KB;
    const int st0  = sa.st[g][0];
    const int st1  = sa.st[g][1];
    const int st2  = sa.st[g][2];

    // Stage full x window (zero-padded) as interleaved split fp16 pairs
    {
        const int gbase = t0 + klo;
        const float* xrow = noise + (size_t)row * IN_SEQ;
        for (int i = tid; i < SXP_LEN; i += THREADS) {
            const int gi = gbase + i;
            float x0 = (gi >= 0     && gi < IN_SEQ)     ? xrow[gi]     : 0.0f;
            float x1 = (gi + 1 >= 0 && gi + 1 < IN_SEQ) ? xrow[gi + 1] : 0.0f;
            float h0 = __half2float(__float2half_rn(x0));
            float h1 = __half2float(__float2half_rn(x1));
            sPhl[i] = make_uint2(packh2(h0, h1), packh2(x0 - h0, x1 - h1));
        }
        if (tid < NF) ss[tid] = scale[f0 + tid];
    }

    const int lane = tid & 31;
    const int w    = tid >> 5;
    const int r    = lane >> 2;
    const int cc   = lane & 3;
    const int mb   = w * 64;
    const int A0   = mb + r + 2 * cc;

    // B staging: each thread handles 16 taps (4 float4) of one filter
    const int bf = tid >> 2;
    const int bq = tid & 3;
    const float* bgsrc = filt + (size_t)(f0 + bf) * KS;

    float acc[4][4][4];
#pragma unroll
    for (int mt = 0; mt < 4; ++mt)
#pragma unroll
        for (int nt = 0; nt < 4; ++nt)
#pragma unroll
            for (int j = 0; j < 4; ++j)
                acc[mt][nt][j] = 0.0f;

    auto ldgB = [&](int ch, float4* v) {
        const int kb = klo + ch * KB + 16 * bq;
#pragma unroll
        for (int i = 0; i < 4; ++i) {
            const int k = kb + 4 * i;
            v[i] = (k >= 0 && k < KS)
                 ? *reinterpret_cast<const float4*>(bgsrc + k)
                 : make_float4(0.f, 0.f, 0.f, 0.f);
        }
    };
    auto stsB = [&](int buf, const float4* v) {
        uint32_t* dst = &sBp[buf * BCH + bf * BROW + 8 * bq];
#pragma unroll
        for (int i = 0; i < 4; ++i) {
            dst[2 * i]     = packh2(v[i].x, v[i].y);
            dst[2 * i + 1] = packh2(v[i].z, v[i].w);
        }
    };

    {
        float4 v[4];
        ldgB(0, v);
        stsB(0, v);
    }
    __syncthreads();

    // Rolling A-fragment buffer: 9 window words for the current k16 step
    uint2 wc[9], wn[9];
#pragma unroll
    for (int j = 0; j < 9; ++j) wc[j] = sPhl[A0 + 8 * j];

    for (int ch = 0; ch < nch; ++ch) {
        float4 pv[4];
        const bool more = (ch + 1) < nch;
        if (more) ldgB(ch + 1, pv);             // overlap LDG with MMAs

        const int buf = ch & 1;
        const bool a0v = (ch >= st0);
        const bool a1v = (ch >= st1);
        const bool a2v = (ch >= st2);

#pragma unroll
        for (int s = 0; s < 4; ++s) {
            // prefetch next step's A words (safe: window zero-padded)
            const int nbase = A0 + ch * KB + 16 * (s + 1);
#pragma unroll
            for (int j = 0; j < 9; ++j) wn[j] = sPhl[nbase + 8 * j];

#pragma unroll
            for (int nt = 0; nt < 4; ++nt) {
                if (nt == 0 && !a0v) continue;
                if (nt == 1 && !a1v) continue;
                if (nt == 2 && !a2v) continue;
                const uint32_t* brow = &sBp[buf * BCH + (nt * 8 + r) * BROW + 8 * s];
                const uint32_t b0 = brow[cc];
                const uint32_t b1 = brow[cc + 4];
#pragma unroll
                for (int mt = 0; mt < 4; ++mt)
                    mma_f16(acc[mt][nt],
                            wc[2 * mt].x, wc[2 * mt + 1].x,
                            wc[2 * mt + 1].x, wc[2 * mt + 2].x,
                            b0, b1);            // xh*fh
#pragma unroll
                for (int mt = 0; mt < 4; ++mt)
                    mma_f16(acc[mt][nt],
                            wc[2 * mt].y, wc[2 * mt + 1].y,
                            wc[2 * mt + 1].y, wc[2 * mt + 2].y,
                            b0, b1);            // xl*fh
            }
#pragma unroll
            for (int j = 0; j < 9; ++j) wc[j] = wn[j];
        }

        if (more) stsB(buf ^ 1, pv);
        __syncthreads();
    }

    // Epilogue: scale + scattered stores
#pragma unroll
    for (int nt = 0; nt < 4; ++nt) {
        const int fA = nt * 8 + 2 * cc;
        const float s0 = ss[fA];
        const float s1 = ss[fA + 1];
        float* o0 = out + ((size_t)row * NFILT + f0 + fA) * T_OUT + t0;
        float* o1 = o0 + T_OUT;
#pragma unroll
        for (int mt = 0; mt < 4; ++mt) {
            const int t = mb + mt * 16 + r;
            o0[t]     = acc[mt][nt][0] * s0;
            o1[t]     = acc[mt][nt][1] * s1;
            o0[t + 8] = acc[mt][nt][2] * s0;
            o1[t + 8] = acc[mt][nt][3] * s1;
        }
    }
}

extern "C" void kernel_launch(void* const* d_in, const int* in_sizes, int n_in,
                              void* d_out, int out_size)
{
    const float* noise = (const float*)d_in[0];   // (2,8,9095)
    const float* filt  = (const float*)d_in[1];   // (128,5000)
    const float* scale = (const float*)d_in[2];   // (1,128,1)
    float* out = (float*)d_out;                   // (2,1024,4096)

    StartArr sa;
    const double l0 = log2(250.0), l1 = log2(10000.0);
    for (int g = 0; g < NG; ++g) {
        int nch_nt[4];
        for (int nt = 0; nt < 4; ++nt) {
            const int i = g * NF + nt * 8 + 7;     // longest filter in n8 tile
            double sr = exp2(l0 + (l1 - l0) * (double)i / 127.0);
            if (sr < 250.0)   sr = 250.0;
            if (sr > 10000.0) sr = 10000.0;
            const int taps = (int)ceil(sr * 0.5);
            nch_nt[nt] = (taps + 8 + KB - 1) / KB;
        }
        const int nmax = nch_nt[3];                // filters ordered by taps
        sa.klo[g] = KS - KB * nmax;                // may be negative (zero pad)
        for (int nt = 0; nt < 4; ++nt)
            sa.st[g][nt] = nmax - nch_nt[nt];
    }

    const int smem_bytes = SXP_LEN * 8 + 2 * BCH * 4 + NF * 4;  // 51200
    cudaFuncSetAttribute(blur_mma_kernel,
                         cudaFuncAttributeMaxDynamicSharedMemorySize, smem_bytes);

    dim3 grid(NG, T_OUT / MT, NROWS);             // (4, 16, 16) = 1024 CTAs
    blur_mma_kernel<<<grid, THREADS, smem_bytes>>>(noise, filt, scale, out, sa);
}

// round 12
// speedup vs baseline: 1.6878x; 1.6878x over previous
#include <cuda_runtime.h>
#include <cuda_fp16.h>
#include <math.h>
#include <stdint.h>

// BlurredNoise via mma.sync fp16 (m16n8k16) implicit GEMM, SINGLE pass.
// D[m=t, n=filter] = sum_k x[t0+m+k] * filt[f0+n, k]
// Both operands rounded to fp16; fp32 accumulate. Measured 2-pass error was
// 2.07e-4 (B-rounding only); adding independent A-rounding gives ~2.9e-4,
// 3.4x under the 1e-3 gate. Halves HMMA instruction count vs R10.
// Per-n8-tile zero-prefix skip kept (bit-identical work elision).

#define KS      5000
#define IN_SEQ  9095
#define T_OUT   4096
#define NFILT   128
#define NROWS   16
#define NG      4
#define NF      32      // filters per group (GEMM N)
#define MT      256     // t per CTA (GEMM M)
#define THREADS 128
#define KB      32      // taps per chunk (2 k16 steps)
#define SXP_LEN 5280    // max wlen = 32*157 + 255 = 5279
#define BROW    17      // uint pairs per filter row (16 + 1 pad)
#define BCH     (NF * BROW)

struct StartArr { int klo[NG]; int st[NG][4]; };

__device__ __forceinline__ uint32_t packh2(float a, float b) {
    __half2 h = __halves2half2(__float2half_rn(a), __float2half_rn(b));
    return *reinterpret_cast<uint32_t*>(&h);
}

__device__ __forceinline__ void mma_f16(float* d,
                                        uint32_t a0, uint32_t a1,
                                        uint32_t a2, uint32_t a3,
                                        uint32_t b0, uint32_t b1) {
    asm volatile(
        "mma.sync.aligned.m16n8k16.row.col.f32.f16.f16.f32 "
        "{%0,%1,%2,%3}, {%4,%5,%6,%7}, {%8,%9}, {%0,%1,%2,%3};"
        : "+f"(d[0]), "+f"(d[1]), "+f"(d[2]), "+f"(d[3])
        : "r"(a0), "r"(a1), "r"(a2), "r"(a3), "r"(b0), "r"(b1));
}

__global__ __launch_bounds__(THREADS)
void blur_mma_kernel(const float* __restrict__ noise,
                     const float* __restrict__ filt,
                     const float* __restrict__ scale,
                     float* __restrict__ out,
                     StartArr sa)
{
    __shared__ uint32_t sPh[SXP_LEN];   // {xh[i], xh[i+1]} fp16 pairs
    __shared__ uint32_t sBp[2][BCH];    // fp16 filter pairs, double-buffered
    __shared__ float ss[NF];

    const int tid  = threadIdx.x;
    const int g    = (NG - 1) - blockIdx.x;     // heavy group first
    const int tb   = blockIdx.y;
    const int row  = blockIdx.z;

    const int t0   = tb * MT;
    const int f0   = g * NF;
    const int klo  = sa.klo[g];                 // may be negative (zero pad)
    const int nch  = (KS - klo) / KB;
    const int st0  = sa.st[g][0];               // first active chunk per nt
    const int st1  = sa.st[g][1];
    const int st2  = sa.st[g][2];

    // Stage x window as fp16 pairs + scales
    {
        const int wlen = KB * nch + MT - 1;
        const int gbase = t0 + klo;
        const float* xrow = noise + (size_t)row * IN_SEQ;
        for (int i = tid; i < wlen; i += THREADS) {
            const int gi = gbase + i;
            float x0 = (gi >= 0     && gi < IN_SEQ)     ? xrow[gi]     : 0.0f;
            float x1 = (gi + 1 >= 0 && gi + 1 < IN_SEQ) ? xrow[gi + 1] : 0.0f;
            sPh[i] = packh2(x0, x1);
        }
        if (tid < NF) ss[tid] = scale[f0 + tid];
    }

    const int lane = tid & 31;
    const int w    = tid >> 5;
    const int r    = lane >> 2;
    const int cc   = lane & 3;
    const int mb   = w * 64;
    const int A0   = mb + r + 2 * cc;   // thread A-frag base within sP

    // B staging: 128 threads, 8 taps (4 pairs) of one filter each
    const int bf = tid >> 2;
    const int bq = tid & 3;
    const float* bgsrc = filt + (size_t)(f0 + bf) * KS;

    float acc[4][4][4];
#pragma unroll
    for (int mt = 0; mt < 4; ++mt)
#pragma unroll
        for (int nt = 0; nt < 4; ++nt)
#pragma unroll
            for (int j = 0; j < 4; ++j)
                acc[mt][nt][j] = 0.0f;

    auto ldgB = [&](int ch, float4& v0, float4& v1) {
        const int k = klo + ch * KB + 8 * bq;   // k ≡ 0 (mod 8)
        if (k >= 0 && k < KS) {
            v0 = *reinterpret_cast<const float4*>(bgsrc + k);
            v1 = *reinterpret_cast<const float4*>(bgsrc + k + 4);
        } else {
            v0 = v1 = make_float4(0.f, 0.f, 0.f, 0.f);
        }
    };
    auto stsB = [&](int buf, float4 v0, float4 v1) {
        uint32_t* dst = &sBp[buf][bf * BROW + 4 * bq];
        dst[0] = packh2(v0.x, v0.y);
        dst[1] = packh2(v0.z, v0.w);
        dst[2] = packh2(v1.x, v1.y);
        dst[3] = packh2(v1.z, v1.w);
    };

    {
        float4 a0, a1;
        ldgB(0, a0, a1);
        stsB(0, a0, a1);
    }
    __syncthreads();

    for (int ch = 0; ch < nch; ++ch) {
        float4 p0, p1;
        const bool more = (ch + 1) < nch;
        if (more) ldgB(ch + 1, p0, p1);         // overlap LDG with MMAs

        const int buf = ch & 1;
        const bool a0v = (ch >= st0);
        const bool a1v = (ch >= st1);
        const bool a2v = (ch >= st2);

#pragma unroll
        for (int s = 0; s < 2; ++s) {           // k16 steps within chunk
            const int base = A0 + ch * KB + 16 * s;

            // A fragments: 9 pair-words cover all 4 m-tiles
            uint32_t wh[9];
#pragma unroll
            for (int j = 0; j < 9; ++j) wh[j] = sPh[base + 8 * j];

#pragma unroll
            for (int nt = 0; nt < 4; ++nt) {
                if (nt == 0 && !a0v) continue;
                if (nt == 1 && !a1v) continue;
                if (nt == 2 && !a2v) continue;
                const uint32_t* brow = &sBp[buf][(nt * 8 + r) * BROW + 8 * s];
                const uint32_t b0 = brow[cc];
                const uint32_t b1 = brow[cc + 4];
#pragma unroll
                for (int mt = 0; mt < 4; ++mt)
                    mma_f16(acc[mt][nt],
                            wh[2 * mt], wh[2 * mt + 1],
                            wh[2 * mt + 1], wh[2 * mt + 2],
                            b0, b1);
            }
        }

        if (more) stsB(buf ^ 1, p0, p1);
        __syncthreads();
    }

    // Epilogue: scale + scattered stores
    // d frag: c0:(r, 2c) c1:(r, 2c+1) c2:(r+8, 2c) c3:(r+8, 2c+1)
#pragma unroll
    for (int nt = 0; nt < 4; ++nt) {
        const int fA = nt * 8 + 2 * cc;
        const float s0 = ss[fA];
        const float s1 = ss[fA + 1];
        float* o0 = out + ((size_t)row * NFILT + f0 + fA) * T_OUT + t0;
        float* o1 = o0 + T_OUT;
#pragma unroll
        for (int mt = 0; mt < 4; ++mt) {
            const int t = mb + mt * 16 + r;
            o0[t]     = acc[mt][nt][0] * s0;
            o1[t]     = acc[mt][nt][1] * s1;
            o0[t + 8] = acc[mt][nt][2] * s0;
            o1[t + 8] = acc[mt][nt][3] * s1;
        }
    }
}

extern "C" void kernel_launch(void* const* d_in, const int* in_sizes, int n_in,
                              void* d_out, int out_size)
{
    const float* noise = (const float*)d_in[0];   // (2,8,9095)
    const float* filt  = (const float*)d_in[1];   // (128,5000)
    const float* scale = (const float*)d_in[2];   // (1,128,1)
    float* out = (float*)d_out;                   // (2,1024,4096)

    StartArr sa;
    const double l0 = log2(250.0), l1 = log2(10000.0);
    for (int g = 0; g < NG; ++g) {
        int nch_nt[4];
        for (int nt = 0; nt < 4; ++nt) {
            const int i = g * NF + nt * 8 + 7;     // longest filter in n8 tile
            double sr = exp2(l0 + (l1 - l0) * (double)i / 127.0);
            if (sr < 250.0)   sr = 250.0;
            if (sr > 10000.0) sr = 10000.0;
            const int taps = (int)ceil(sr * 0.5);
            nch_nt[nt] = (taps + 8 + KB - 1) / KB;
        }
        const int nmax = nch_nt[3];                // filters ordered by taps
        sa.klo[g] = KS - KB * nmax;                // may be negative (zero pad)
        for (int nt = 0; nt < 4; ++nt)
            sa.st[g][nt] = nmax - nch_nt[nt];
    }

    dim3 grid(NG, T_OUT / MT, NROWS);             // (4, 16, 16) = 1024 CTAs
    blur_mma_kernel<<<grid, THREADS>>>(noise, filt, scale, out, sa);
}

// round 13
// speedup vs baseline: 2.0019x; 1.1861x over previous
#include <cuda_runtime.h>
#include <cuda_fp16.h>
#include <math.h>
#include <stdint.h>

// BlurredNoise via mma.sync fp16 (m16n8k16) implicit GEMM, single pass.
// R13: B pre-converted to fp16 pairs in a padded __device__ global buffer by a
// pre-pass kernel; mainloop warps LDG their own B fragments (ping-pong double
// buffer) -> NO __syncthreads / STS in the mainloop. A-window LDS 18->11 per
// chunk via k16-step overlap. Per-n8-tile zero-prefix skip kept.

#define KS      5000
#define IN_SEQ  9095
#define T_OUT   4096
#define NFILT   128
#define NROWS   16
#define NG      4
#define NF      32      // filters per group (GEMM N)
#define MT      256     // t per CTA (GEMM M)
#define THREADS 128
#define KB      32      // taps per chunk (2 k16 steps)
#define SXP_LEN 5328    // >= max A index 5325 (nch even => klo >= -56)
#define BPAD    32      // zero pad words each side of each filter row
#define BROWG   (2500 + 2 * BPAD)   // uint32 pair-words per filter row

struct StartArr { int klo[NG]; int st[NG][4]; };

__device__ uint32_t gBp[NFILT][BROWG];   // fp16 filter pairs, zero-padded

__device__ __forceinline__ uint32_t packh2(float a, float b) {
    __half2 h = __halves2half2(__float2half_rn(a), __float2half_rn(b));
    return *reinterpret_cast<uint32_t*>(&h);
}

__device__ __forceinline__ void mma_f16(float* d,
                                        uint32_t a0, uint32_t a1,
                                        uint32_t a2, uint32_t a3,
                                        uint32_t b0, uint32_t b1) {
    asm volatile(
        "mma.sync.aligned.m16n8k16.row.col.f32.f16.f16.f32 "
        "{%0,%1,%2,%3}, {%4,%5,%6,%7}, {%8,%9}, {%0,%1,%2,%3};"
        : "+f"(d[0]), "+f"(d[1]), "+f"(d[2]), "+f"(d[3])
        : "r"(a0), "r"(a1), "r"(a2), "r"(a3), "r"(b0), "r"(b1));
}

// Pre-pass: convert filt rows to fp16 pairs, zero the pads.
__global__ void cvt_kernel(const float* __restrict__ filt)
{
    const int n = blockIdx.x;
    const int t = threadIdx.x;
    if (t < BPAD) {
        gBp[n][t] = 0u;
        gBp[n][BROWG - BPAD + t] = 0u;
    }
    const float2* src = reinterpret_cast<const float2*>(filt + (size_t)n * KS);
    for (int q = t; q < KS / 2; q += blockDim.x) {
        float2 v = src[q];
        gBp[n][BPAD + q] = packh2(v.x, v.y);
    }
}

__global__ __launch_bounds__(THREADS)
void blur_mma_kernel(const float* __restrict__ noise,
                     const float* __restrict__ scale,
                     float* __restrict__ out,
                     StartArr sa)
{
    __shared__ uint32_t sPh[SXP_LEN];   // {x[i], x[i+1]} fp16 pairs
    __shared__ float ss[NF];

    const int tid  = threadIdx.x;
    const int g    = (NG - 1) - blockIdx.x;     // heavy group first
    const int tb   = blockIdx.y;
    const int row  = blockIdx.z;

    const int t0   = tb * MT;
    const int f0   = g * NF;
    const int klo  = sa.klo[g];                 // even, may be negative
    const int nch  = (KS - klo) / KB;           // even by construction
    const int st0  = sa.st[g][0];
    const int st1  = sa.st[g][1];
    const int st2  = sa.st[g][2];

    // Stage x window as fp16 pairs (full array, zero-padded) + scales
    {
        const int gbase = t0 + klo;
        const float* xrow = noise + (size_t)row * IN_SEQ;
        for (int i = tid; i < SXP_LEN; i += THREADS) {
            const int gi = gbase + i;
            float x0 = (gi >= 0     && gi < IN_SEQ)     ? xrow[gi]     : 0.0f;
            float x1 = (gi + 1 >= 0 && gi + 1 < IN_SEQ) ? xrow[gi + 1] : 0.0f;
            sPh[i] = packh2(x0, x1);
        }
        if (tid < NF) ss[tid] = scale[f0 + tid];
    }
    __syncthreads();                            // the ONLY barrier

    const int lane = tid & 31;
    const int w    = tid >> 5;
    const int r    = lane >> 2;
    const int cc   = lane & 3;
    const int mb   = w * 64;
    const int A0   = mb + r + 2 * cc;

    // Per-thread B row pointers (pair-word units), origin at tap klo
    const uint32_t* bp0 = &gBp[f0 +  0 + r][BPAD + klo / 2 + cc];
    const uint32_t* bp1 = &gBp[f0 +  8 + r][BPAD + klo / 2 + cc];
    const uint32_t* bp2 = &gBp[f0 + 16 + r][BPAD + klo / 2 + cc];
    const uint32_t* bp3 = &gBp[f0 + 24 + r][BPAD + klo / 2 + cc];

    float acc[4][4][4];
#pragma unroll
    for (int mt = 0; mt < 4; ++mt)
#pragma unroll
        for (int nt = 0; nt < 4; ++nt)
#pragma unroll
            for (int j = 0; j < 4; ++j)
                acc[mt][nt][j] = 0.0f;

    // B fragment regs: [nt][s*2 + {b0,b1}]
    uint32_t bc[4][4], bn[4][4];

#define LDB(dst, qoff)                                                  \
    do {                                                                \
        _Pragma("unroll")                                               \
        for (int _s = 0; _s < 2; ++_s) {                                \
            dst[0][2*_s]   = bp0[(qoff) + 8*_s];                        \
            dst[0][2*_s+1] = bp0[(qoff) + 8*_s + 4];                    \
            dst[1][2*_s]   = bp1[(qoff) + 8*_s];                        \
            dst[1][2*_s+1] = bp1[(qoff) + 8*_s + 4];                    \
            dst[2][2*_s]   = bp2[(qoff) + 8*_s];                        \
            dst[2][2*_s+1] = bp2[(qoff) + 8*_s + 4];                    \
            dst[3][2*_s]   = bp3[(qoff) + 8*_s];                        \
            dst[3][2*_s+1] = bp3[(qoff) + 8*_s + 4];                    \
        }                                                               \
    } while (0)

#define CHUNK_BODY(ch, bcur, bnext)                                     \
    do {                                                                \
        LDB(bnext, ((ch) + 1) * 16);        /* prefetch next chunk */   \
        const bool v0 = ((ch) >= st0);                                  \
        const bool v1 = ((ch) >= st1);                                  \
        const bool v2 = ((ch) >= st2);                                  \
        /* A window: 11 pair-words cover both k16 steps */              \
        uint32_t wa[11];                                                \
        const int base = A0 + (ch) * KB;                                \
        _Pragma("unroll")                                               \
        for (int j = 0; j < 11; ++j) wa[j] = sPh[base + 8 * j];         \
        _Pragma("unroll")                                               \
        for (int s = 0; s < 2; ++s) {                                   \
            const int o = 2 * s;                                        \
            _Pragma("unroll")                                           \
            for (int nt = 0; nt < 4; ++nt) {                            \
                if (nt == 0 && !v0) continue;                           \
                if (nt == 1 && !v1) continue;                           \
                if (nt == 2 && !v2) continue;                           \
                const uint32_t b0 = bcur[nt][2*s];                      \
                const uint32_t b1 = bcur[nt][2*s+1];                    \
                _Pragma("unroll")                                       \
                for (int mt = 0; mt < 4; ++mt)                          \
                    mma_f16(acc[mt][nt],                                \
                            wa[2*mt+o], wa[2*mt+1+o],                   \
                            wa[2*mt+1+o], wa[2*mt+2+o],                 \
                            b0, b1);                                    \
            }                                                           \
        }                                                               \
    } while (0)

    LDB(bc, 0);
    for (int ch = 0; ch < nch; ch += 2) {
        CHUNK_BODY(ch,     bc, bn);
        CHUNK_BODY(ch + 1, bn, bc);
    }

    // Epilogue: scale + scattered stores
#pragma unroll
    for (int nt = 0; nt < 4; ++nt) {
        const int fA = nt * 8 + 2 * cc;
        const float s0 = ss[fA];
        const float s1 = ss[fA + 1];
        float* o0 = out + ((size_t)row * NFILT + f0 + fA) * T_OUT + t0;
        float* o1 = o0 + T_OUT;
#pragma unroll
        for (int mt = 0; mt < 4; ++mt) {
            const int t = mb + mt * 16 + r;
            o0[t]     = acc[mt][nt][0] * s0;
            o1[t]     = acc[mt][nt][1] * s1;
            o0[t + 8] = acc[mt][nt][2] * s0;
            o1[t + 8] = acc[mt][nt][3] * s1;
        }
    }
}

extern "C" void kernel_launch(void* const* d_in, const int* in_sizes, int n_in,
                              void* d_out, int out_size)
{
    const float* noise = (const float*)d_in[0];   // (2,8,9095)
    const float* filt  = (const float*)d_in[1];   // (128,5000)
    const float* scale = (const float*)d_in[2];   // (1,128,1)
    float* out = (float*)d_out;                   // (2,1024,4096)

    StartArr sa;
    const double l0 = log2(250.0), l1 = log2(10000.0);
    for (int g = 0; g < NG; ++g) {
        int nch_nt[4];
        for (int nt = 0; nt < 4; ++nt) {
            const int i = g * NF + nt * 8 + 7;     // longest filter in n8 tile
            double sr = exp2(l0 + (l1 - l0) * (double)i / 127.0);
            if (sr < 250.0)   sr = 250.0;
            if (sr > 10000.0) sr = 10000.0;
            const int taps = (int)ceil(sr * 0.5);
            nch_nt[nt] = (taps + 8 + KB - 1) / KB;
        }
        int nmax = nch_nt[3];                      // filters ordered by taps
        if (nmax & 1) nmax++;                      // even: ping-pong pairs
        sa.klo[g] = KS - KB * nmax;                // may be negative (padded)
        for (int nt = 0; nt < 4; ++nt)
            sa.st[g][nt] = nmax - nch_nt[nt];
    }

    cvt_kernel<<<NFILT, 256>>>(filt);

    dim3 grid(NG, T_OUT / MT, NROWS);             // (4, 16, 16) = 1024 CTAs
    blur_mma_kernel<<<grid, THREADS>>>(noise, scale, out, sa);
}

// round 14
// speedup vs baseline: 2.1364x; 1.0672x over previous
#include <cuda_runtime.h>
#include <cuda_fp16.h>
#include <math.h>
#include <stdint.h>

// BlurredNoise via mma.sync fp16 (m16n8k16) implicit GEMM, single pass.
// R14: B pre-converted AND permuted so each thread's (b0,b1) fragment pair is
// one aligned LDG.64 (8 per chunk vs 16 LDG.32). Unconditional prefetch
// (reads stay in row padding). No barriers in mainloop (from R13).

#define KS      5000
#define IN_SEQ  9095
#define T_OUT   4096
#define NFILT   128
#define NROWS   16
#define NG      4
#define NF      32      // filters per group (GEMM N)
#define MT      256     // t per CTA (GEMM M)
#define THREADS 128
#define KB      32      // taps per chunk (2 k16 steps)
#define SXP_LEN 5328    // >= max A index 5309
#define BPAD    32      // zero pad words each side of each filter row
#define BROWG   (2500 + 2 * BPAD)   // uint32 pair-words per filter row (2564)

struct StartArr { int klo[NG]; int st[NG][4]; };

__device__ uint2 gBp2[NFILT][BROWG / 2];   // permuted fp16 filter pairs

__device__ __forceinline__ uint32_t packh2(float a, float b) {
    __half2 h = __halves2half2(__float2half_rn(a), __float2half_rn(b));
    return *reinterpret_cast<uint32_t*>(&h);
}

__device__ __forceinline__ void mma_f16(float* d,
                                        uint32_t a0, uint32_t a1,
                                        uint32_t a2, uint32_t a3,
                                        uint32_t b0, uint32_t b1) {
    asm volatile(
        "mma.sync.aligned.m16n8k16.row.col.f32.f16.f16.f32 "
        "{%0,%1,%2,%3}, {%4,%5,%6,%7}, {%8,%9}, {%0,%1,%2,%3};"
        : "+f"(d[0]), "+f"(d[1]), "+f"(d[2]), "+f"(d[3])
        : "r"(a0), "r"(a1), "r"(a2), "r"(a3), "r"(b0), "r"(b1));
}

// Pre-pass: convert filt rows to fp16 pairs with the LDG.64 permutation.
// Consumption groups of 8 words start at padded-word-index ≡ 4 (mod 8)
// (invariant: klo ≡ 8 mod 16 for all groups). Within a group, word order
// [0,4,1,5,2,6,3,7] so thread cc's (b0,b1) = one aligned uint2 at 2cc.
__global__ void cvt_kernel(const float* __restrict__ filt)
{
    const int n = blockIdx.x;
    uint32_t* row = reinterpret_cast<uint32_t*>(gBp2[n]);
    for (int i = threadIdx.x; i < BROWG; i += blockDim.x) row[i] = 0u;
    __syncthreads();
    const float2* src = reinterpret_cast<const float2*>(filt + (size_t)n * KS);
    for (int q = threadIdx.x; q < KS / 2; q += blockDim.x) {
        float2 v = src[q];
        const int W   = BPAD + q;
        const int g8  = (W - 4) >> 3;
        const int pos = (W - 4) & 7;
        const int np  = (pos < 4) ? (2 * pos) : (2 * (pos - 4) + 1);
        row[4 + 8 * g8 + np] = packh2(v.x, v.y);
    }
}

__global__ __launch_bounds__(THREADS)
void blur_mma_kernel(const float* __restrict__ noise,
                     const float* __restrict__ scale,
                     float* __restrict__ out,
                     StartArr sa)
{
    __shared__ uint32_t sPh[SXP_LEN];   // {x[i], x[i+1]} fp16 pairs
    __shared__ float ss[NF];

    const int tid  = threadIdx.x;
    const int g    = (NG - 1) - blockIdx.x;     // heavy group first
    const int tb   = blockIdx.y;
    const int row  = blockIdx.z;

    const int t0   = tb * MT;
    const int f0   = g * NF;
    const int klo  = sa.klo[g];                 // ≡ 8 mod 16, may be negative
    const int nch  = (KS - klo) / KB;           // even
    const int st0  = sa.st[g][0];
    const int st1  = sa.st[g][1];
    const int st2  = sa.st[g][2];

    const int lane = tid & 31;
    const int w    = tid >> 5;
    const int r    = lane >> 2;
    const int cc   = lane & 3;
    const int mb   = w * 64;
    const int A0   = mb + r + 2 * cc;

    // Per-thread permuted B pointers (uint2): group id of (ch,s) = G0+2ch+s,
    // uint2 index = 2 + 4*g8 + cc  ->  base + 4*(2ch+s).
    const int G0 = (BPAD + klo / 2 - 4) >> 3;
    const uint2* bq0 = &gBp2[f0 +  0 + r][2 + 4 * G0 + cc];
    const uint2* bq1 = &gBp2[f0 +  8 + r][2 + 4 * G0 + cc];
    const uint2* bq2 = &gBp2[f0 + 16 + r][2 + 4 * G0 + cc];
    const uint2* bq3 = &gBp2[f0 + 24 + r][2 + 4 * G0 + cc];

    // B fragment regs: [nt][s*2 + {b0,b1}]
    uint32_t bc[4][4], bn[4][4];

#define LDB(dst, ch)                                                    \
    do {                                                                \
        _Pragma("unroll")                                               \
        for (int _s = 0; _s < 2; ++_s) {                                \
            const int _o = 4 * (2 * (ch) + _s);                         \
            uint2 _t;                                                   \
            _t = bq0[_o]; dst[0][2*_s] = _t.x; dst[0][2*_s+1] = _t.y;   \
            _t = bq1[_o]; dst[1][2*_s] = _t.x; dst[1][2*_s+1] = _t.y;   \
            _t = bq2[_o]; dst[2][2*_s] = _t.x; dst[2][2*_s+1] = _t.y;   \
            _t = bq3[_o]; dst[3][2*_s] = _t.x; dst[3][2*_s+1] = _t.y;   \
        }                                                               \
    } while (0)

    LDB(bc, 0);                                 // hide under x staging

    // Stage x window as fp16 pairs (full array, zero-padded) + scales
    {
        const int gbase = t0 + klo;
        const float* xrow = noise + (size_t)row * IN_SEQ;
        for (int i = tid; i < SXP_LEN; i += THREADS) {
            const int gi = gbase + i;
            float x0 = (gi >= 0     && gi < IN_SEQ)     ? xrow[gi]     : 0.0f;
            float x1 = (gi + 1 >= 0 && gi + 1 < IN_SEQ) ? xrow[gi + 1] : 0.0f;
            sPh[i] = packh2(x0, x1);
        }
        if (tid < NF) ss[tid] = scale[f0 + tid];
    }
    __syncthreads();                            // the ONLY barrier

    float acc[4][4][4];
#pragma unroll
    for (int mt = 0; mt < 4; ++mt)
#pragma unroll
        for (int nt = 0; nt < 4; ++nt)
#pragma unroll
            for (int j = 0; j < 4; ++j)
                acc[mt][nt][j] = 0.0f;

#define CHUNK_BODY(ch, bcur, bnext)                                     \
    do {                                                                \
        LDB(bnext, (ch) + 1);  /* tail prefetch stays in row padding */ \
        const bool v0 = ((ch) >= st0);                                  \
        const bool v1 = ((ch) >= st1);                                  \
        const bool v2 = ((ch) >= st2);                                  \
        uint32_t wa[11];                                                \
        const int base = A0 + (ch) * KB;                                \
        _Pragma("unroll")                                               \
        for (int j = 0; j < 11; ++j) wa[j] = sPh[base + 8 * j];         \
        _Pragma("unroll")                                               \
        for (int s = 0; s < 2; ++s) {                                   \
            const int o = 2 * s;                                        \
            _Pragma("unroll")                                           \
            for (int nt = 0; nt < 4; ++nt) {                            \
                if (nt == 0 && !v0) continue;                           \
                if (nt == 1 && !v1) continue;                           \
                if (nt == 2 && !v2) continue;                           \
                const uint32_t b0 = bcur[nt][2*s];                      \
                const uint32_t b1 = bcur[nt][2*s+1];                    \
                _Pragma("unroll")                                       \
                for (int mt = 0; mt < 4; ++mt)                          \
                    mma_f16(acc[mt][nt],                                \
                            wa[2*mt+o], wa[2*mt+1+o],                   \
                            wa[2*mt+1+o], wa[2*mt+2+o],                 \
                            b0, b1);                                    \
            }                                                           \
        }                                                               \
    } while (0)

    for (int ch = 0; ch < nch; ch += 2) {
        CHUNK_BODY(ch,     bc, bn);
        CHUNK_BODY(ch + 1, bn, bc);
    }

    // Epilogue: scale + scattered stores
#pragma unroll
    for (int nt = 0; nt < 4; ++nt) {
        const int fA = nt * 8 + 2 * cc;
        const float s0 = ss[fA];
        const float s1 = ss[fA + 1];
        float* o0 = out + ((size_t)row * NFILT + f0 + fA) * T_OUT + t0;
        float* o1 = o0 + T_OUT;
#pragma unroll
        for (int mt = 0; mt < 4; ++mt) {
            const int t = mb + mt * 16 + r;
            o0[t]     = acc[mt][nt][0] * s0;
            o1[t]     = acc[mt][nt][1] * s1;
            o0[t + 8] = acc[mt][nt][2] * s0;
            o1[t + 8] = acc[mt][nt][3] * s1;
        }
    }
}

extern "C" void kernel_launch(void* const* d_in, const int* in_sizes, int n_in,
                              void* d_out, int out_size)
{
    const float* noise = (const float*)d_in[0];   // (2,8,9095)
    const float* filt  = (const float*)d_in[1];   // (128,5000)
    const float* scale = (const float*)d_in[2];   // (1,128,1)
    float* out = (float*)d_out;                   // (2,1024,4096)

    StartArr sa;
    const double l0 = log2(250.0), l1 = log2(10000.0);
    for (int g = 0; g < NG; ++g) {
        int nch_nt[4];
        for (int nt = 0; nt < 4; ++nt) {
            const int i = g * NF + nt * 8 + 7;     // longest filter in n8 tile
            double sr = exp2(l0 + (l1 - l0) * (double)i / 127.0);
            if (sr < 250.0)   sr = 250.0;
            if (sr > 10000.0) sr = 10000.0;
            const int taps = (int)ceil(sr * 0.5);
            nch_nt[nt] = (taps + 8 + KB - 1) / KB;
        }
        int nmax = nch_nt[3];                      // filters ordered by taps
        if (nmax & 1) nmax++;                      // even: ping-pong pairs
        sa.klo[g] = KS - KB * nmax;                // ≡ 8 mod 16, may be < 0
        for (int nt = 0; nt < 4; ++nt)
            sa.st[g][nt] = nmax - nch_nt[nt];
    }

    cvt_kernel<<<NFILT, 256>>>(filt);

    dim3 grid(NG, T_OUT / MT, NROWS);             // (4, 16, 16) = 1024 CTAs
    blur_mma_kernel<<<grid, THREADS>>>(noise, scale, out, sa);
}

// round 15
// speedup vs baseline: 2.1865x; 1.0234x over previous
#include <cuda_runtime.h>
#include <cuda_fp16.h>
#include <math.h>
#include <stdint.h>

// BlurredNoise via mma.sync fp16 (m16n8k16) implicit GEMM, single pass.
// R15: split-K for the heaviest filter group (two slices, fp32 atomicAdd into
// a zero-initialized output region) to kill the load-imbalance critical path.
// Keeps R14's permuted-B LDG.64 fragments and barrier-free mainloop.

#define KS      5000
#define IN_SEQ  9095
#define T_OUT   4096
#define NFILT   128
#define NROWS   16
#define NG      4
#define NDESC   5
#define NF      32      // filters per group (GEMM N)
#define MT      256     // t per CTA (GEMM M)
#define THREADS 128
#define KB      32      // taps per chunk (2 k16 steps)
#define SXP_LEN 3520    // >= max slice window (100 chunks): 3200+255+overrun
#define BPAD    32      // zero pad words each side of each filter row
#define BROWG   (2500 + 2 * BPAD)   // uint32 pair-words per filter row (2564)

struct Desc { int f0, klo, nch, st0, st1, st2, atom; };
struct DescArr { Desc d[NDESC]; };

__device__ uint2 gBp2[NFILT][BROWG / 2];   // permuted fp16 filter pairs

__device__ __forceinline__ uint32_t packh2(float a, float b) {
    __half2 h = __halves2half2(__float2half_rn(a), __float2half_rn(b));
    return *reinterpret_cast<uint32_t*>(&h);
}

__device__ __forceinline__ void mma_f16(float* d,
                                        uint32_t a0, uint32_t a1,
                                        uint32_t a2, uint32_t a3,
                                        uint32_t b0, uint32_t b1) {
    asm volatile(
        "mma.sync.aligned.m16n8k16.row.col.f32.f16.f16.f32 "
        "{%0,%1,%2,%3}, {%4,%5,%6,%7}, {%8,%9}, {%0,%1,%2,%3};"
        : "+f"(d[0]), "+f"(d[1]), "+f"(d[2]), "+f"(d[3])
        : "r"(a0), "r"(a1), "r"(a2), "r"(a3), "r"(b0), "r"(b1));
}

// Pre-pass 1: convert filt rows to fp16 pairs with the LDG.64 permutation.
__global__ void cvt_kernel(const float* __restrict__ filt)
{
    const int n = blockIdx.x;
    uint32_t* row = reinterpret_cast<uint32_t*>(gBp2[n]);
    for (int i = threadIdx.x; i < BROWG; i += blockDim.x) row[i] = 0u;
    __syncthreads();
    const float2* src = reinterpret_cast<const float2*>(filt + (size_t)n * KS);
    for (int q = threadIdx.x; q < KS / 2; q += blockDim.x) {
        float2 v = src[q];
        const int W   = BPAD + q;
        const int g8  = (W - 4) >> 3;
        const int pos = (W - 4) & 7;
        const int np  = (pos < 4) ? (2 * pos) : (2 * (pos - 4) + 1);
        row[4 + 8 * g8 + np] = packh2(v.x, v.y);
    }
}

// Pre-pass 2: zero the split group's output region (filters [96,128)).
__global__ void zero_kernel(float* __restrict__ out)
{
    const int idx = blockIdx.x * blockDim.x + threadIdx.x;
    const int per_row = NF * T_OUT;                       // 131072
    const int row = idx / per_row;
    const int rem = idx - row * per_row;
    if (row < NROWS)
        out[((size_t)row * NFILT + 96) * T_OUT + rem] = 0.0f;
}

__global__ __launch_bounds__(THREADS)
void blur_mma_kernel(const float* __restrict__ noise,
                     const float* __restrict__ scale,
                     float* __restrict__ out,
                     DescArr da)
{
    __shared__ uint32_t sPh[SXP_LEN];   // {x[i], x[i+1]} fp16 pairs
    __shared__ float ss[NF];

    const int tid  = threadIdx.x;
    const Desc dd  = da.d[blockIdx.x];
    const int tb   = blockIdx.y;
    const int row  = blockIdx.z;

    const int t0   = tb * MT;
    const int f0   = dd.f0;
    const int klo  = dd.klo;                    // ≡ 8 mod 16, may be negative
    const int nch  = dd.nch;                    // even
    const int st0  = dd.st0;
    const int st1  = dd.st1;
    const int st2  = dd.st2;

    const int lane = tid & 31;
    const int w    = tid >> 5;
    const int r    = lane >> 2;
    const int cc   = lane & 3;
    const int mb   = w * 64;
    const int A0   = mb + r + 2 * cc;

    // Per-thread permuted B pointers (uint2)
    const int G0 = (BPAD + klo / 2 - 4) >> 3;
    const uint2* bq0 = &gBp2[f0 +  0 + r][2 + 4 * G0 + cc];
    const uint2* bq1 = &gBp2[f0 +  8 + r][2 + 4 * G0 + cc];
    const uint2* bq2 = &gBp2[f0 + 16 + r][2 + 4 * G0 + cc];
    const uint2* bq3 = &gBp2[f0 + 24 + r][2 + 4 * G0 + cc];

    uint32_t bc[4][4], bn[4][4];

#define LDB(dst, ch)                                                    \
    do {                                                                \
        _Pragma("unroll")                                               \
        for (int _s = 0; _s < 2; ++_s) {                                \
            const int _o = 4 * (2 * (ch) + _s);                         \
            uint2 _t;                                                   \
            _t = bq0[_o]; dst[0][2*_s] = _t.x; dst[0][2*_s+1] = _t.y;   \
            _t = bq1[_o]; dst[1][2*_s] = _t.x; dst[1][2*_s+1] = _t.y;   \
            _t = bq2[_o]; dst[2][2*_s] = _t.x; dst[2][2*_s+1] = _t.y;   \
            _t = bq3[_o]; dst[3][2*_s] = _t.x; dst[3][2*_s+1] = _t.y;   \
        }                                                               \
    } while (0)

    LDB(bc, 0);                                 // hide under x staging

    // Stage x window (slice range, zero-padded) + scales
    {
        const int gbase = t0 + klo;
        const float* xrow = noise + (size_t)row * IN_SEQ;
        for (int i = tid; i < SXP_LEN; i += THREADS) {
            const int gi = gbase + i;
            float x0 = (gi >= 0     && gi < IN_SEQ)     ? xrow[gi]     : 0.0f;
            float x1 = (gi + 1 >= 0 && gi + 1 < IN_SEQ) ? xrow[gi + 1] : 0.0f;
            sPh[i] = packh2(x0, x1);
        }
        if (tid < NF) ss[tid] = scale[f0 + tid];
    }
    __syncthreads();                            // the ONLY barrier

    float acc[4][4][4];
#pragma unroll
    for (int mt = 0; mt < 4; ++mt)
#pragma unroll
        for (int nt = 0; nt < 4; ++nt)
#pragma unroll
            for (int j = 0; j < 4; ++j)
                acc[mt][nt][j] = 0.0f;

#define CHUNK_BODY(ch, bcur, bnext)                                     \
    do {                                                                \
        LDB(bnext, (ch) + 1);  /* tail prefetch stays in row padding */ \
        const bool v0 = ((ch) >= st0);                                  \
        const bool v1 = ((ch) >= st1);                                  \
        const bool v2 = ((ch) >= st2);                                  \
        uint32_t wa[11];                                                \
        const int base = A0 + (ch) * KB;                                \
        _Pragma("unroll")                                               \
        for (int j = 0; j < 11; ++j) wa[j] = sPh[base + 8 * j];         \
        _Pragma("unroll")                                               \
        for (int s = 0; s < 2; ++s) {                                   \
            const int o = 2 * s;                                        \
            _Pragma("unroll")                                           \
            for (int nt = 0; nt < 4; ++nt) {                            \
                if (nt == 0 && !v0) continue;                           \
                if (nt == 1 && !v1) continue;                           \
                if (nt == 2 && !v2) continue;                           \
                const uint32_t b0 = bcur[nt][2*s];                      \
                const uint32_t b1 = bcur[nt][2*s+1];                    \
                _Pragma("unroll")                                       \
                for (int mt = 0; mt < 4; ++mt)                          \
                    mma_f16(acc[mt][nt],                                \
                            wa[2*mt+o], wa[2*mt+1+o],                   \
                            wa[2*mt+1+o], wa[2*mt+2+o],                 \
                            b0, b1);                                    \
            }                                                           \
        }                                                               \
    } while (0)

    for (int ch = 0; ch < nch; ch += 2) {
        CHUNK_BODY(ch,     bc, bn);
        CHUNK_BODY(ch + 1, bn, bc);
    }

    // Epilogue: scale + store (or accumulate for split-K slices)
#pragma unroll
    for (int nt = 0; nt < 4; ++nt) {
        const int fA = nt * 8 + 2 * cc;
        const float s0 = ss[fA];
        const float s1 = ss[fA + 1];
        float* o0 = out + ((size_t)row * NFILT + f0 + fA) * T_OUT + t0;
        float* o1 = o0 + T_OUT;
        if (dd.atom) {
#pragma unroll
            for (int mt = 0; mt < 4; ++mt) {
                const int t = mb + mt * 16 + r;
                atomicAdd(&o0[t],     acc[mt][nt][0] * s0);
                atomicAdd(&o1[t],     acc[mt][nt][1] * s1);
                atomicAdd(&o0[t + 8], acc[mt][nt][2] * s0);
                atomicAdd(&o1[t + 8], acc[mt][nt][3] * s1);
            }
        } else {
#pragma unroll
            for (int mt = 0; mt < 4; ++mt) {
                const int t = mb + mt * 16 + r;
                o0[t]     = acc[mt][nt][0] * s0;
                o1[t]     = acc[mt][nt][1] * s1;
                o0[t + 8] = acc[mt][nt][2] * s0;
                o1[t + 8] = acc[mt][nt][3] * s1;
            }
        }
    }
}

extern "C" void kernel_launch(void* const* d_in, const int* in_sizes, int n_in,
                              void* d_out, int out_size)
{
    const float* noise = (const float*)d_in[0];   // (2,8,9095)
    const float* filt  = (const float*)d_in[1];   // (128,5000)
    const float* scale = (const float*)d_in[2];   // (1,128,1)
    float* out = (float*)d_out;                   // (2,1024,4096)

    // Per-group chunk geometry
    int nmaxg[NG], stg[NG][4];
    const double l0 = log2(250.0), l1 = log2(10000.0);
    for (int g = 0; g < NG; ++g) {
        int nch_nt[4];
        for (int nt = 0; nt < 4; ++nt) {
            const int i = g * NF + nt * 8 + 7;
            double sr = exp2(l0 + (l1 - l0) * (double)i / 127.0);
            if (sr < 250.0)   sr = 250.0;
            if (sr > 10000.0) sr = 10000.0;
            const int taps = (int)ceil(sr * 0.5);
            nch_nt[nt] = (taps + 8 + KB - 1) / KB;
        }
        int nmax = nch_nt[3];
        if (nmax & 1) nmax++;
        nmaxg[g] = nmax;
        for (int nt = 0; nt < 4; ++nt) stg[g][nt] = nmax - nch_nt[nt];
    }

    // Split group 3 at the equal-MMA-work even chunk boundary
    int split = 0;
    {
        const int n3 = nmaxg[3];
        int total = 0;
        for (int ch = 0; ch < n3; ++ch)
            for (int nt = 0; nt < 3; ++nt) total += (ch >= stg[3][nt]);
        total += n3;
        int run = 0, best = 1 << 30;
        for (int ch = 0; ch < n3; ++ch) {
            for (int nt = 0; nt < 3; ++nt) run += (ch >= stg[3][nt]);
            run += 1;
            if (!((ch + 1) & 1)) {
                const int diff = abs(2 * run - total);
                if (diff < best) { best = diff; split = ch + 1; }
            }
        }
    }

    DescArr da;
    auto mk = [&](int slot, int g, int ch0, int ch1, int atom) {
        Desc& d = da.d[slot];
        d.f0  = g * NF;
        d.klo = KS - KB * nmaxg[g] + KB * ch0;
        d.nch = ch1 - ch0;
        d.st0 = stg[g][0] - ch0; if (d.st0 < 0) d.st0 = 0;
        d.st1 = stg[g][1] - ch0; if (d.st1 < 0) d.st1 = 0;
        d.st2 = stg[g][2] - ch0; if (d.st2 < 0) d.st2 = 0;
        d.atom = atom;
    };
    mk(0, 3, split, nmaxg[3], 1);   // dense g3 tail (heaviest) first
    mk(1, 3, 0, split, 1);
    mk(2, 2, 0, nmaxg[2], 0);
    mk(3, 1, 0, nmaxg[1], 0);
    mk(4, 0, 0, nmaxg[0], 0);

    cvt_kernel<<<NFILT, 256>>>(filt);
    {
        const int n = NROWS * NF * T_OUT;
        zero_kernel<<<(n + 255) / 256, 256>>>(out);
    }

    dim3 grid(NDESC, T_OUT / MT, NROWS);          // (5, 16, 16) = 1280 CTAs
    blur_mma_kernel<<<grid, THREADS>>>(noise, scale, out, da);
}

// round 16
// speedup vs baseline: 2.2640x; 1.0354x over previous
#include <cuda_runtime.h>
#include <cuda_fp16.h>
#include <math.h>
#include <stdint.h>

// BlurredNoise via mma.sync fp16 (m16n8k16) implicit GEMM, single pass.
// R16: fused + parallelized pre-pass (B fp16 permute via gather formulation,
// 2 blocks/row, plus zeroing of the split-group output region in the same
// launch). Main GEMM kernel identical to R15 (split-K heavy group, permuted-B
// LDG.64 fragments, barrier-free mainloop).

#define KS      5000
#define IN_SEQ  9095
#define T_OUT   4096
#define NFILT   128
#define NROWS   16
#define NG      4
#define NDESC   5
#define NF      32      // filters per group (GEMM N)
#define MT      256     // t per CTA (GEMM M)
#define THREADS 128
#define KB      32      // taps per chunk (2 k16 steps)
#define SXP_LEN 3520    // >= max slice window (100 chunks)
#define BPAD    32      // zero pad words each side of each filter row
#define BROWG   (2500 + 2 * BPAD)   // uint32 pair-words per filter row (2564)

#define CVT_BLKS  256   // 2 blocks per filter row
#define ZERO_BLKS 64
#define PREP_BLKS (CVT_BLKS + ZERO_BLKS)

struct Desc { int f0, klo, nch, st0, st1, st2, atom; };
struct DescArr { Desc d[NDESC]; };

__device__ uint2 gBp2[NFILT][BROWG / 2];   // permuted fp16 filter pairs

__device__ __forceinline__ uint32_t packh2(float a, float b) {
    __half2 h = __halves2half2(__float2half_rn(a), __float2half_rn(b));
    return *reinterpret_cast<uint32_t*>(&h);
}

__device__ __forceinline__ void mma_f16(float* d,
                                        uint32_t a0, uint32_t a1,
                                        uint32_t a2, uint32_t a3,
                                        uint32_t b0, uint32_t b1) {
    asm volatile(
        "mma.sync.aligned.m16n8k16.row.col.f32.f16.f16.f32 "
        "{%0,%1,%2,%3}, {%4,%5,%6,%7}, {%8,%9}, {%0,%1,%2,%3};"
        : "+f"(d[0]), "+f"(d[1]), "+f"(d[2]), "+f"(d[3])
        : "r"(a0), "r"(a1), "r"(a2), "r"(a3), "r"(b0), "r"(b1));
}

// Fused pre-pass.
// Blocks [0, CVT_BLKS): permuted fp16 conversion, GATHER form (write-once,
//   each output word computes its source tap) -> no zero-init, no races.
//   Permuted layout: groups of 8 words at (i-4)>>3, order [0,4,1,5,2,6,3,7].
// Blocks [CVT_BLKS, PREP_BLKS): zero the split-group output (filters [96,128)).
__global__ void prep_kernel(const float* __restrict__ filt,
                            float* __restrict__ out)
{
    const int bx = blockIdx.x;
    if (bx < CVT_BLKS) {
        const int n    = bx >> 1;
        const int half = bx & 1;
        uint32_t* row  = reinterpret_cast<uint32_t*>(gBp2[n]);
        const float* src = filt + (size_t)n * KS;
        const int i0 = half * (BROWG / 2);
        const int i1 = i0 + (BROWG / 2);
        for (int i = i0 + threadIdx.x; i < i1; i += blockDim.x) {
            uint32_t v = 0u;
            const int gi = i - 4;
            if (gi >= 0 && i < BROWG - 32) {
                const int g8  = gi >> 3;
                const int np  = gi & 7;
                const int pos = (np & 1) ? (4 + (np >> 1)) : (np >> 1);
                const int q   = 4 + 8 * g8 + pos - BPAD;   // source pair index
                if (q >= 0 && q < KS / 2)
                    v = packh2(src[2 * q], src[2 * q + 1]);
            }
            row[i] = v;
        }
    } else {
        // zero out[:, 96:128, :] = 16 * 32 * 4096 floats, float4 stores
        const int zb  = bx - CVT_BLKS;
        const int tot = NROWS * NF * T_OUT / 4;            // float4 count
        const int per_row = NF * T_OUT / 4;                // 32768
        const float4 z = make_float4(0.f, 0.f, 0.f, 0.f);
        for (int i = zb * blockDim.x + threadIdx.x; i < tot;
             i += ZERO_BLKS * blockDim.x) {
            const int row = i / per_row;
            const int rem = i - row * per_row;
            reinterpret_cast<float4*>(
                out + ((size_t)row * NFILT + 96) * T_OUT)[rem] = z;
        }
    }
}

__global__ __launch_bounds__(THREADS)
void blur_mma_kernel(const float* __restrict__ noise,
                     const float* __restrict__ scale,
                     float* __restrict__ out,
                     DescArr da)
{
    __shared__ uint32_t sPh[SXP_LEN];   // {x[i], x[i+1]} fp16 pairs
    __shared__ float ss[NF];

    const int tid  = threadIdx.x;
    const Desc dd  = da.d[blockIdx.x];
    const int tb   = blockIdx.y;
    const int row  = blockIdx.z;

    const int t0   = tb * MT;
    const int f0   = dd.f0;
    const int klo  = dd.klo;                    // ≡ 8 mod 16, may be negative
    const int nch  = dd.nch;                    // even
    const int st0  = dd.st0;
    const int st1  = dd.st1;
    const int st2  = dd.st2;

    const int lane = tid & 31;
    const int w    = tid >> 5;
    const int r    = lane >> 2;
    const int cc   = lane & 3;
    const int mb   = w * 64;
    const int A0   = mb + r + 2 * cc;

    // Per-thread permuted B pointers (uint2)
    const int G0 = (BPAD + klo / 2 - 4) >> 3;
    const uint2* bq0 = &gBp2[f0 +  0 + r][2 + 4 * G0 + cc];
    const uint2* bq1 = &gBp2[f0 +  8 + r][2 + 4 * G0 + cc];
    const uint2* bq2 = &gBp2[f0 + 16 + r][2 + 4 * G0 + cc];
    const uint2* bq3 = &gBp2[f0 + 24 + r][2 + 4 * G0 + cc];

    uint32_t bc[4][4], bn[4][4];

#define LDB(dst, ch)                                                    \
    do {                                                                \
        _Pragma("unroll")                                               \
        for (int _s = 0; _s < 2; ++_s) {                                \
            const int _o = 4 * (2 * (ch) + _s);                         \
            uint2 _t;                                                   \
            _t = bq0[_o]; dst[0][2*_s] = _t.x; dst[0][2*_s+1] = _t.y;   \
            _t = bq1[_o]; dst[1][2*_s] = _t.x; dst[1][2*_s+1] = _t.y;   \
            _t = bq2[_o]; dst[2][2*_s] = _t.x; dst[2][2*_s+1] = _t.y;   \
            _t = bq3[_o]; dst[3][2*_s] = _t.x; dst[3][2*_s+1] = _t.y;   \
        }                                                               \
    } while (0)

    LDB(bc, 0);                                 // hide under x staging

    // Stage x window (slice range, zero-padded) + scales
    {
        const int gbase = t0 + klo;
        const float* xrow = noise + (size_t)row * IN_SEQ;
        for (int i = tid; i < SXP_LEN; i += THREADS) {
            const int gi = gbase + i;
            float x0 = (gi >= 0     && gi < IN_SEQ)     ? xrow[gi]     : 0.0f;
            float x1 = (gi + 1 >= 0 && gi + 1 < IN_SEQ) ? xrow[gi + 1] : 0.0f;
            sPh[i] = packh2(x0, x1);
        }
        if (tid < NF) ss[tid] = scale[f0 + tid];
    }
    __syncthreads();                            // the ONLY barrier

    float acc[4][4][4];
#pragma unroll
    for (int mt = 0; mt < 4; ++mt)
#pragma unroll
        for (int nt = 0; nt < 4; ++nt)
#pragma unroll
            for (int j = 0; j < 4; ++j)
                acc[mt][nt][j] = 0.0f;

#define CHUNK_BODY(ch, bcur, bnext)                                     \
    do {                                                                \
        LDB(bnext, (ch) + 1);  /* tail prefetch stays in row padding */ \
        const bool v0 = ((ch) >= st0);                                  \
        const bool v1 = ((ch) >= st1);                                  \
        const bool v2 = ((ch) >= st2);                                  \
        uint32_t wa[11];                                                \
        const int base = A0 + (ch) * KB;                                \
        _Pragma("unroll")                                               \
        for (int j = 0; j < 11; ++j) wa[j] = sPh[base + 8 * j];         \
        _Pragma("unroll")                                               \
        for (int s = 0; s < 2; ++s) {                                   \
            const int o = 2 * s;                                        \
            _Pragma("unroll")                                           \
            for (int nt = 0; nt < 4; ++nt) {                            \
                if (nt == 0 && !v0) continue;                           \
                if (nt == 1 && !v1) continue;                           \
                if (nt == 2 && !v2) continue;                           \
                const uint32_t b0 = bcur[nt][2*s];                      \
                const uint32_t b1 = bcur[nt][2*s+1];                    \
                _Pragma("unroll")                                       \
                for (int mt = 0; mt < 4; ++mt)                          \
                    mma_f16(acc[mt][nt],                                \
                            wa[2*mt+o], wa[2*mt+1+o],                   \
                            wa[2*mt+1+o], wa[2*mt+2+o],                 \
                            b0, b1);                                    \
            }                                                           \
        }                                                               \
    } while (0)

    for (int ch = 0; ch < nch; ch += 2) {
        CHUNK_BODY(ch,     bc, bn);
        CHUNK_BODY(ch + 1, bn, bc);
    }

    // Epilogue: scale + store (or accumulate for split-K slices)
#pragma unroll
    for (int nt = 0; nt < 4; ++nt) {
        const int fA = nt * 8 + 2 * cc;
        const float s0 = ss[fA];
        const float s1 = ss[fA + 1];
        float* o0 = out + ((size_t)row * NFILT + f0 + fA) * T_OUT + t0;
        float* o1 = o0 + T_OUT;
        if (dd.atom) {
#pragma unroll
            for (int mt = 0; mt < 4; ++mt) {
                const int t = mb + mt * 16 + r;
                atomicAdd(&o0[t],     acc[mt][nt][0] * s0);
                atomicAdd(&o1[t],     acc[mt][nt][1] * s1);
                atomicAdd(&o0[t + 8], acc[mt][nt][2] * s0);
                atomicAdd(&o1[t + 8], acc[mt][nt][3] * s1);
            }
        } else {
#pragma unroll
            for (int mt = 0; mt < 4; ++mt) {
                const int t = mb + mt * 16 + r;
                o0[t]     = acc[mt][nt][0] * s0;
                o1[t]     = acc[mt][nt][1] * s1;
                o0[t + 8] = acc[mt][nt][2] * s0;
                o1[t + 8] = acc[mt][nt][3] * s1;
            }
        }
    }
}

extern "C" void kernel_launch(void* const* d_in, const int* in_sizes, int n_in,
                              void* d_out, int out_size)
{
    const float* noise = (const float*)d_in[0];   // (2,8,9095)
    const float* filt  = (const float*)d_in[1];   // (128,5000)
    const float* scale = (const float*)d_in[2];   // (1,128,1)
    float* out = (float*)d_out;                   // (2,1024,4096)

    // Per-group chunk geometry
    int nmaxg[NG], stg[NG][4];
    const double l0 = log2(250.0), l1 = log2(10000.0);
    for (int g = 0; g < NG; ++g) {
        int nch_nt[4];
        for (int nt = 0; nt < 4; ++nt) {
            const int i = g * NF + nt * 8 + 7;
            double sr = exp2(l0 + (l1 - l0) * (double)i / 127.0);
            if (sr < 250.0)   sr = 250.0;
            if (sr > 10000.0) sr = 10000.0;
            const int taps = (int)ceil(sr * 0.5);
            nch_nt[nt] = (taps + 8 + KB - 1) / KB;
        }
        int nmax = nch_nt[3];
        if (nmax & 1) nmax++;
        nmaxg[g] = nmax;
        for (int nt = 0; nt < 4; ++nt) stg[g][nt] = nmax - nch_nt[nt];
    }

    // Split group 3 at the equal-MMA-work even chunk boundary
    int split = 0;
    {
        const int n3 = nmaxg[3];
        int total = 0;
        for (int ch = 0; ch < n3; ++ch)
            for (int nt = 0; nt < 3; ++nt) total += (ch >= stg[3][nt]);
        total += n3;
        int run = 0, best = 1 << 30;
        for (int ch = 0; ch < n3; ++ch) {
            for (int nt = 0; nt < 3; ++nt) run += (ch >= stg[3][nt]);
            run += 1;
            if (!((ch + 1) & 1)) {
                const int diff = abs(2 * run - total);
                if (diff < best) { best = diff; split = ch + 1; }
            }
        }
    }

    DescArr da;
    auto mk = [&](int slot, int g, int ch0, int ch1, int atom) {
        Desc& d = da.d[slot];
        d.f0  = g * NF;
        d.klo = KS - KB * nmaxg[g] + KB * ch0;
        d.nch = ch1 - ch0;
        d.st0 = stg[g][0] - ch0; if (d.st0 < 0) d.st0 = 0;
        d.st1 = stg[g][1] - ch0; if (d.st1 < 0) d.st1 = 0;
        d.st2 = stg[g][2] - ch0; if (d.st2 < 0) d.st2 = 0;
        d.atom = atom;
    };
    mk(0, 3, split, nmaxg[3], 1);   // dense g3 tail (heaviest) first
    mk(1, 3, 0, split, 1);
    mk(2, 2, 0, nmaxg[2], 0);
    mk(3, 1, 0, nmaxg[1], 0);
    mk(4, 0, 0, nmaxg[0], 0);

    prep_kernel<<<PREP_BLKS, 256>>>(filt, out);

    dim3 grid(NDESC, T_OUT / MT, NROWS);          // (5, 16, 16) = 1280 CTAs
    blur_mma_kernel<<<grid, THREADS>>>(noise, scale, out, da);
}

// round 17
// speedup vs baseline: 2.4474x; 1.0810x over previous
#include <cuda_runtime.h>
#include <cuda_fp16.h>
#include <math.h>
#include <stdint.h>

// BlurredNoise via mma.sync fp16 (m16n8k16) implicit GEMM, single pass.
// R17: B stored in FRAGMENT ORDER — gBlin[g][step][ntpair][lane] as uint4 —
// so each chunk's B is 4 fully-coalesced LDG.128 (16 L1 wavefronts vs ~64
// scattered sectors in R16). Split-K heavy group + barrier-free mainloop kept.

#define KS      5000
#define IN_SEQ  9095
#define T_OUT   4096
#define NFILT   128
#define NROWS   16
#define NG      4
#define NDESC   5
#define NF      32      // filters per group (GEMM N)
#define MT      256     // t per CTA (GEMM M)
#define THREADS 128
#define KB      32      // taps per chunk (2 k16 steps)
#define SXP_LEN 3520    // >= max slice window (100 chunks)
#define NSTEP   336     // k16 steps per group incl. pads (max used: 330)
#define SPAD    8       // step pad for negative klo (min s_glob = -4)

#define CVT_BLKS  336   // NG*NSTEP*64 threads / 256
#define ZERO_BLKS 64
#define PREP_BLKS (CVT_BLKS + ZERO_BLKS)

struct Desc { int f0, klo, nch, st0, st1, st2, atom; };
struct DescArr { Desc d[NDESC]; };

// Fragment-ordered B: [group][k16 step][nt pair][lane(r*4+cc)]
// uint4 = { nt_a.b0, nt_a.b1, nt_b.b0, nt_b.b1 },  nt_a=2*pair, nt_b=2*pair+1
__device__ uint4 gBlin[NG][NSTEP][2][32];

__device__ __forceinline__ uint32_t packh2(float a, float b) {
    __half2 h = __halves2half2(__float2half_rn(a), __float2half_rn(b));
    return *reinterpret_cast<uint32_t*>(&h);
}

__device__ __forceinline__ void mma_f16(float* d,
                                        uint32_t a0, uint32_t a1,
                                        uint32_t a2, uint32_t a3,
                                        uint32_t b0, uint32_t b1) {
    asm volatile(
        "mma.sync.aligned.m16n8k16.row.col.f32.f16.f16.f32 "
        "{%0,%1,%2,%3}, {%4,%5,%6,%7}, {%8,%9}, {%0,%1,%2,%3};"
        : "+f"(d[0]), "+f"(d[1]), "+f"(d[2]), "+f"(d[3])
        : "r"(a0), "r"(a1), "r"(a2), "r"(a3), "r"(b0), "r"(b1));
}

// Fused pre-pass: fragment-order B conversion + zero split-group output.
// B word for (f, step s_glob, cc, b): source pair q = 4 + 8*s_glob + cc + 4*b
// (pair units; tap k = 2q), zero outside [0, KS/2).
__global__ void prep_kernel(const float* __restrict__ filt,
                            float* __restrict__ out)
{
    const int bx = blockIdx.x;
    if (bx < CVT_BLKS) {
        const int idx   = bx * 256 + threadIdx.x;   // over NG*NSTEP*2*32
        const int lane  = idx & 31;
        const int pair  = (idx >> 5) & 1;
        const int s_idx = (idx >> 6) % NSTEP;
        const int g     = idx / (NSTEP * 64);
        const int r     = lane >> 2;
        const int cc    = lane & 3;
        const int q0    = 4 + 8 * (s_idx - SPAD) + cc;
        const int q1    = q0 + 4;
        const int fa    = g * NF + pair * 16 + r;   // nt = 2*pair
        const int fb    = fa + 8;                   // nt = 2*pair + 1
        const float* ra = filt + (size_t)fa * KS;
        const float* rb = filt + (size_t)fb * KS;
        uint4 v = make_uint4(0u, 0u, 0u, 0u);
        if (q0 >= 0 && q0 < KS / 2) {
            v.x = packh2(ra[2 * q0], ra[2 * q0 + 1]);
            v.z = packh2(rb[2 * q0], rb[2 * q0 + 1]);
        }
        if (q1 >= 0 && q1 < KS / 2) {
            v.y = packh2(ra[2 * q1], ra[2 * q1 + 1]);
            v.w = packh2(rb[2 * q1], rb[2 * q1 + 1]);
        }
        gBlin[g][s_idx][pair][lane] = v;
    } else {
        // zero out[:, 96:128, :] with float4 stores
        const int zb  = bx - CVT_BLKS;
        const int tot = NROWS * NF * T_OUT / 4;
        const int per_row = NF * T_OUT / 4;
        const float4 z = make_float4(0.f, 0.f, 0.f, 0.f);
        for (int i = zb * blockDim.x + threadIdx.x; i < tot;
             i += ZERO_BLKS * blockDim.x) {
            const int row = i / per_row;
            const int rem = i - row * per_row;
            reinterpret_cast<float4*>(
                out + ((size_t)row * NFILT + 96) * T_OUT)[rem] = z;
        }
    }
}

__global__ __launch_bounds__(THREADS)
void blur_mma_kernel(const float* __restrict__ noise,
                     const float* __restrict__ scale,
                     float* __restrict__ out,
                     DescArr da)
{
    __shared__ uint32_t sPh[SXP_LEN];   // {x[i], x[i+1]} fp16 pairs
    __shared__ float ss[NF];

    const int tid  = threadIdx.x;
    const Desc dd  = da.d[blockIdx.x];
    const int tb   = blockIdx.y;
    const int row  = blockIdx.z;

    const int t0   = tb * MT;
    const int f0   = dd.f0;
    const int klo  = dd.klo;                    // ≡ 8 mod 32, may be negative
    const int nch  = dd.nch;
    const int st0  = dd.st0;
    const int st1  = dd.st1;
    const int st2  = dd.st2;

    const int lane = tid & 31;
    const int w    = tid >> 5;
    const int r    = lane >> 2;
    const int cc   = lane & 3;
    const int mb   = w * 64;
    const int A0   = mb + r + 2 * cc;

    // Fragment-ordered B base: step id S0 for chunk 0, step s of chunk ch
    // lives at uint4 index ((S0 + 2*ch + s)*2 + pair)*32 + lane.
    const int S0 = (klo - 8) / 16 + SPAD;       // exact: klo ≡ 8 mod 32
    const uint4* btp = &gBlin[f0 >> 5][0][0][lane];

    uint32_t bc[4][4], bn[4][4];

#define LDB(dst, ch)                                                    \
    do {                                                                \
        _Pragma("unroll")                                               \
        for (int _s = 0; _s < 2; ++_s) {                                \
            const int _st = S0 + 2 * (ch) + _s;                         \
            const uint4 _t0 = btp[(_st * 2 + 0) * 32];                  \
            const uint4 _t1 = btp[(_st * 2 + 1) * 32];                  \
            dst[0][2*_s] = _t0.x; dst[0][2*_s+1] = _t0.y;               \
            dst[1][2*_s] = _t0.z; dst[1][2*_s+1] = _t0.w;               \
            dst[2][2*_s] = _t1.x; dst[2][2*_s+1] = _t1.y;               \
            dst[3][2*_s] = _t1.z; dst[3][2*_s+1] = _t1.w;               \
        }                                                               \
    } while (0)

    LDB(bc, 0);                                 // hide under x staging

    // Stage x window (slice range, zero-padded) + scales
    {
        const int gbase = t0 + klo;
        const float* xrow = noise + (size_t)row * IN_SEQ;
        for (int i = tid; i < SXP_LEN; i += THREADS) {
            const int gi = gbase + i;
            float x0 = (gi >= 0     && gi < IN_SEQ)     ? xrow[gi]     : 0.0f;
            float x1 = (gi + 1 >= 0 && gi + 1 < IN_SEQ) ? xrow[gi + 1] : 0.0f;
            sPh[i] = packh2(x0, x1);
        }
        if (tid < NF) ss[tid] = scale[f0 + tid];
    }
    __syncthreads();                            // the ONLY barrier

    float acc[4][4][4];
#pragma unroll
    for (int mt = 0; mt < 4; ++mt)
#pragma unroll
        for (int nt = 0; nt < 4; ++nt)
#pragma unroll
            for (int j = 0; j < 4; ++j)
                acc[mt][nt][j] = 0.0f;

#define CHUNK_BODY(ch, bcur, bnext)                                     \
    do {                                                                \
        LDB(bnext, (ch) + 1);   /* tail prefetch stays in step pads */  \
        const bool v0 = ((ch) >= st0);                                  \
        const bool v1 = ((ch) >= st1);                                  \
        const bool v2 = ((ch) >= st2);                                  \
        uint32_t wa[11];                                                \
        const int base = A0 + (ch) * KB;                                \
        _Pragma("unroll")                                               \
        for (int j = 0; j < 11; ++j) wa[j] = sPh[base + 8 * j];         \
        _Pragma("unroll")                                               \
        for (int s = 0; s < 2; ++s) {                                   \
            const int o = 2 * s;                                        \
            _Pragma("unroll")                                           \
            for (int nt = 0; nt < 4; ++nt) {                            \
                if (nt == 0 && !v0) continue;                           \
                if (nt == 1 && !v1) continue;                           \
                if (nt == 2 && !v2) continue;                           \
                const uint32_t b0 = bcur[nt][2*s];                      \
                const uint32_t b1 = bcur[nt][2*s+1];                    \
                _Pragma("unroll")                                       \
                for (int mt = 0; mt < 4; ++mt)                          \
                    mma_f16(acc[mt][nt],                                \
                            wa[2*mt+o], wa[2*mt+1+o],                   \
                            wa[2*mt+1+o], wa[2*mt+2+o],                 \
                            b0, b1);                                    \
            }                                                           \
        }                                                               \
    } while (0)

    for (int ch = 0; ch < nch; ch += 2) {
        CHUNK_BODY(ch,     bc, bn);
        CHUNK_BODY(ch + 1, bn, bc);
    }

    // Epilogue: scale + store (or accumulate for split-K slices)
#pragma unroll
    for (int nt = 0; nt < 4; ++nt) {
        const int fA = nt * 8 + 2 * cc;
        const float s0 = ss[fA];
        const float s1 = ss[fA + 1];
        float* o0 = out + ((size_t)row * NFILT + f0 + fA) * T_OUT + t0;
        float* o1 = o0 + T_OUT;
        if (dd.atom) {
#pragma unroll
            for (int mt = 0; mt < 4; ++mt) {
                const int t = mb + mt * 16 + r;
                atomicAdd(&o0[t],     acc[mt][nt][0] * s0);
                atomicAdd(&o1[t],     acc[mt][nt][1] * s1);
                atomicAdd(&o0[t + 8], acc[mt][nt][2] * s0);
                atomicAdd(&o1[t + 8], acc[mt][nt][3] * s1);
            }
        } else {
#pragma unroll
            for (int mt = 0; mt < 4; ++mt) {
                const int t = mb + mt * 16 + r;
                o0[t]     = acc[mt][nt][0] * s0;
                o1[t]     = acc[mt][nt][1] * s1;
                o0[t + 8] = acc[mt][nt][2] * s0;
                o1[t + 8] = acc[mt][nt][3] * s1;
            }
        }
    }
}

extern "C" void kernel_launch(void* const* d_in, const int* in_sizes, int n_in,
                              void* d_out, int out_size)
{
    const float* noise = (const float*)d_in[0];   // (2,8,9095)
    const float* filt  = (const float*)d_in[1];   // (128,5000)
    const float* scale = (const float*)d_in[2];   // (1,128,1)
    float* out = (float*)d_out;                   // (2,1024,4096)

    // Per-group chunk geometry
    int nmaxg[NG], stg[NG][4];
    const double l0 = log2(250.0), l1 = log2(10000.0);
    for (int g = 0; g < NG; ++g) {
        int nch_nt[4];
        for (int nt = 0; nt < 4; ++nt) {
            const int i = g * NF + nt * 8 + 7;
            double sr = exp2(l0 + (l1 - l0) * (double)i / 127.0);
            if (sr < 250.0)   sr = 250.0;
            if (sr > 10000.0) sr = 10000.0;
            const int taps = (int)ceil(sr * 0.5);
            nch_nt[nt] = (taps + 8 + KB - 1) / KB;
        }
        int nmax = nch_nt[3];
        if (nmax & 1) nmax++;
        nmaxg[g] = nmax;
        for (int nt = 0; nt < 4; ++nt) stg[g][nt] = nmax - nch_nt[nt];
    }

    // Split group 3 at the equal-MMA-work even chunk boundary
    int split = 0;
    {
        const int n3 = nmaxg[3];
        int total = 0;
        for (int ch = 0; ch < n3; ++ch)
            for (int nt = 0; nt < 3; ++nt) total += (ch >= stg[3][nt]);
        total += n3;
        int run = 0, best = 1 << 30;
        for (int ch = 0; ch < n3; ++ch) {
            for (int nt = 0; nt < 3; ++nt) run += (ch >= stg[3][nt]);
            run += 1;
            if (!((ch + 1) & 1)) {
                const int diff = abs(2 * run - total);
                if (diff < best) { best = diff; split = ch + 1; }
            }
        }
    }

    DescArr da;
    auto mk = [&](int slot, int g, int ch0, int ch1, int atom) {
        Desc& d = da.d[slot];
        d.f0  = g * NF;
        d.klo = KS - KB * nmaxg[g] + KB * ch0;
        d.nch = ch1 - ch0;
        d.st0 = stg[g][0] - ch0; if (d.st0 < 0) d.st0 = 0;
        d.st1 = stg[g][1] - ch0; if (d.st1 < 0) d.st1 = 0;
        d.st2 = stg[g][2] - ch0; if (d.st2 < 0) d.st2 = 0;
        d.atom = atom;
    };
    mk(0, 3, split, nmaxg[3], 1);   // dense g3 tail (heaviest) first
    mk(1, 3, 0, split, 1);
    mk(2, 2, 0, nmaxg[2], 0);
    mk(3, 1, 0, nmaxg[1], 0);
    mk(4, 0, 0, nmaxg[0], 0);

    prep_kernel<<<PREP_BLKS, 256>>>(filt, out);

    dim3 grid(NDESC, T_OUT / MT, NROWS);          // (5, 16, 16) = 1280 CTAs
    blur_mma_kernel<<<grid, THREADS>>>(noise, scale, out, da);
}